// round 12
// baseline (speedup 1.0000x reference)
#include <cuda_runtime.h>

#define BQ   64
#define BK   64
#define DIM  256
#define SEQ  2048
#define NBAT 8
#define RS   66          // transposed-tile row stride (floats); 66 % 8 == 2 -> conflict-free
#define NTHREADS 256

// smem layout (floats):
// Qs [DIM][RS]  : Qs[d][q]   (transposed)
// Ks [DIM][RS]  : Ks[d][k]   (transposed)
// Vs [BK][DIM]  : Vs[k][d]   (natural)
// Ps [BQ][65]   : probabilities tile
// Ms [BK]       : padding-mask (0/1) for current key block
#define SMEM_FLOATS (2*DIM*RS + BK*DIM + BQ*65 + BK)

__device__ __forceinline__ float rowmax16(float v) {
    #pragma unroll
    for (int o = 8; o > 0; o >>= 1)
        v = fmaxf(v, __shfl_xor_sync(0xffffffffu, v, o));
    return v;
}
__device__ __forceinline__ float rowsum16(float v) {
    #pragma unroll
    for (int o = 8; o > 0; o >>= 1)
        v += __shfl_xor_sync(0xffffffffu, v, o);
    return v;
}

__global__ __launch_bounds__(NTHREADS, 1)
void sdpa_kernel(const float* __restrict__ Q, const float* __restrict__ K,
                 const float* __restrict__ V, const unsigned* __restrict__ Mask,
                 float* __restrict__ O)
{
    extern __shared__ float sm[];
    float* Qs = sm;                    // DIM*RS
    float* Ks = Qs + DIM * RS;         // DIM*RS
    float* Vs = Ks + DIM * RS;         // BK*DIM
    float* Ps = Vs + BK * DIM;         // BQ*65
    float* Ms = Ps + BQ * 65;          // BK

    const int b    = blockIdx.y;
    const int qb   = gridDim.x - 1 - blockIdx.x;   // longest CTAs scheduled first
    const int tid  = threadIdx.x;
    const int warp = tid >> 5;
    const int lane = tid & 31;
    const int tx   = tid & 15;   // column group
    const int ty   = tid >> 4;   // row group

    const float* Qg = Q + ((size_t)b * SEQ + (size_t)qb * BQ) * DIM;
    const float* Kg = K + (size_t)b * SEQ * DIM;
    const float* Vg = V + (size_t)b * SEQ * DIM;
    const unsigned* Mg = Mask + (size_t)b * SEQ;

    const int q8 = lane >> 2;    // 0..7 : row within warp's 8-row group
    const int dg = lane & 3;     // 0..3 : float4 slot within 16-float d-chunk

    // ---- load Q block transposed: Qs[d][q] ----
    {
        const int row = warp * 8 + q8;               // warp owns 8 rows
        #pragma unroll
        for (int it = 0; it < 16; it++) {            // 16 d-chunks of 16 floats
            int d0 = it * 16 + dg * 4;
            float4 v = *(const float4*)(Qg + row * DIM + d0);
            Qs[(d0 + 0) * RS + row] = v.x;
            Qs[(d0 + 1) * RS + row] = v.y;
            Qs[(d0 + 2) * RS + row] = v.z;
            Qs[(d0 + 3) * RS + row] = v.w;
        }
    }

    float acc[4][16];
    #pragma unroll
    for (int i = 0; i < 4; i++)
        #pragma unroll
        for (int u = 0; u < 16; u++) acc[i][u] = 0.f;
    float mrow[4], lrow[4];
    #pragma unroll
    for (int i = 0; i < 4; i++) { mrow[i] = -1e30f; lrow[i] = 0.f; }

    const int qg0 = qb * BQ + 4 * ty;

    for (int kb = 0; kb <= qb; kb++) {
        __syncthreads();   // prev PV done reading Vs/Ps before overwrite

        // ---- load K block transposed: Ks[d][k] ----
        {
            const float* Kb = Kg + (size_t)kb * BK * DIM;
            const int row = warp * 8 + q8;
            #pragma unroll
            for (int it = 0; it < 16; it++) {
                int d0 = it * 16 + dg * 4;
                float4 v = *(const float4*)(Kb + row * DIM + d0);
                Ks[(d0 + 0) * RS + row] = v.x;
                Ks[(d0 + 1) * RS + row] = v.y;
                Ks[(d0 + 2) * RS + row] = v.z;
                Ks[(d0 + 3) * RS + row] = v.w;
            }
        }
        // ---- load V block natural: Vs[k][d] ----
        {
            const float* Vb = Vg + (size_t)kb * BK * DIM;
            #pragma unroll
            for (int it = 0; it < 16; it++) {
                int f = tid + NTHREADS * it;          // float4 index
                int row = f >> 6;
                int c4  = (f & 63) * 4;
                *(float4*)(Vs + row * DIM + c4) = *(const float4*)(Vb + row * DIM + c4);
            }
        }
        // ---- padding mask (robust to int32 {0,1} or f32 {0.0,1.0}) ----
        if (tid < BK) Ms[tid] = (Mg[kb * BK + tid] != 0u) ? 1.f : 0.f;

        __syncthreads();

        // ---- S = Q K^T / 16 : per-thread 4x4 tile ----
        float s[4][4];
        #pragma unroll
        for (int i = 0; i < 4; i++)
            #pragma unroll
            for (int j = 0; j < 4; j++) s[i][j] = 0.f;

        {
            const float* ap = Qs + 4 * ty;
            const float* bp = Ks + tx;
            #pragma unroll 8
            for (int kd = 0; kd < DIM; kd++) {
                float a0 = ap[kd * RS + 0];
                float a1 = ap[kd * RS + 1];
                float a2 = ap[kd * RS + 2];
                float a3 = ap[kd * RS + 3];
                float b0 = bp[kd * RS + 0];
                float b1 = bp[kd * RS + 16];
                float b2 = bp[kd * RS + 32];
                float b3 = bp[kd * RS + 48];
                s[0][0] += a0 * b0; s[0][1] += a0 * b1; s[0][2] += a0 * b2; s[0][3] += a0 * b3;
                s[1][0] += a1 * b0; s[1][1] += a1 * b1; s[1][2] += a1 * b2; s[1][3] += a1 * b3;
                s[2][0] += a2 * b0; s[2][1] += a2 * b1; s[2][2] += a2 * b2; s[2][3] += a2 * b3;
                s[3][0] += a3 * b0; s[3][1] += a3 * b1; s[3][2] += a3 * b2; s[3][3] += a3 * b3;
            }
        }

        const bool fullblk = (kb < qb);   // strictly-below-diagonal: causal always true
        float mv[4];
        #pragma unroll
        for (int j = 0; j < 4; j++) mv[j] = Ms[tx + 16 * j];

        #pragma unroll
        for (int i = 0; i < 4; i++) {
            const int qg = qg0 + i;
            // mask into sentinel
            #pragma unroll
            for (int j = 0; j < 4; j++) {
                int kg = kb * BK + tx + 16 * j;
                bool valid = (mv[j] != 0.f) && (fullblk || kg <= qg);
                float sv = s[i][j] * 0.0625f;   // 1/sqrt(256)
                s[i][j] = valid ? sv : -1e30f;
            }
            float mx = fmaxf(fmaxf(s[i][0], s[i][1]), fmaxf(s[i][2], s[i][3]));
            mx = rowmax16(mx);
            float mnew = fmaxf(mrow[i], mx);
            float corr = __expf(mrow[i] - mnew);  // -1e30 - -1e30 = 0 -> 1 (l=0, harmless)
            float rs = 0.f;
            #pragma unroll
            for (int j = 0; j < 4; j++) {
                float p = (s[i][j] > -1e29f) ? __expf(s[i][j] - mnew) : 0.f;
                rs += p;
                Ps[(4 * ty + i) * 65 + tx + 16 * j] = p;
            }
            rs = rowsum16(rs);
            lrow[i] = lrow[i] * corr + rs;
            mrow[i] = mnew;
            #pragma unroll
            for (int u = 0; u < 16; u++) acc[i][u] *= corr;
        }

        __syncthreads();   // Ps visible to all tx of each row group

        // ---- acc += P V ----
        {
            const float* pp = Ps + 4 * ty * 65;
            const float* vp = Vs + tx;
            #pragma unroll 2
            for (int kk = 0; kk < BK; kk++) {
                float p0 = pp[0 * 65 + kk];
                float p1 = pp[1 * 65 + kk];
                float p2 = pp[2 * 65 + kk];
                float p3 = pp[3 * 65 + kk];
                #pragma unroll
                for (int u = 0; u < 16; u++) {
                    float vv = vp[kk * DIM + 16 * u];
                    acc[0][u] += p0 * vv;
                    acc[1][u] += p1 * vv;
                    acc[2][u] += p2 * vv;
                    acc[3][u] += p3 * vv;
                }
            }
        }
    }

    // ---- epilogue: out = acc / (l + eps) ----
    #pragma unroll
    for (int i = 0; i < 4; i++) {
        float inv = 1.0f / (lrow[i] + 1e-7f);
        float* op = O + ((size_t)b * SEQ + (size_t)(qg0 + i)) * DIM + tx;
        #pragma unroll
        for (int u = 0; u < 16; u++)
            op[16 * u] = acc[i][u] * inv;
    }
}

extern "C" void kernel_launch(void* const* d_in, const int* in_sizes, int n_in,
                              void* d_out, int out_size)
{
    const float*    Q  = (const float*)d_in[0];
    const float*    K  = (const float*)d_in[1];
    const float*    V  = (const float*)d_in[2];
    const unsigned* Mk = (const unsigned*)d_in[3];
    float* O = (float*)d_out;

    size_t smem = SMEM_FLOATS * sizeof(float);   // 217,600 B
    cudaFuncSetAttribute(sdpa_kernel, cudaFuncAttributeMaxDynamicSharedMemorySize, (int)smem);

    dim3 grid(SEQ / BQ, NBAT);
    sdpa_kernel<<<grid, NTHREADS, smem>>>(Q, K, V, Mk, O);
}

// round 13
// speedup vs baseline: 1.0028x; 1.0028x over previous
#include <cuda_runtime.h>

#define BQ   64
#define BK   64
#define DIM  256
#define SEQ  2048
#define NBAT 8
#define RS   66          // transposed-tile row stride (floats); 66 % 8 == 2 -> conflict-free
#define NTHREADS 256

// smem layout (floats):
// Qs [DIM][RS]  : Qs[d][q]   (transposed)
// Ks [DIM][RS]  : Ks[d][k]   (transposed)
// Vs [BK][DIM]  : Vs[k][d]   (natural)
// Ps [BQ][65]   : probabilities tile
// Ms [BK]       : padding-mask (0/1) for current key block
#define SMEM_FLOATS (2*DIM*RS + BK*DIM + BQ*65 + BK)

__device__ __forceinline__ float rowmax16(float v) {
    #pragma unroll
    for (int o = 8; o > 0; o >>= 1)
        v = fmaxf(v, __shfl_xor_sync(0xffffffffu, v, o));
    return v;
}
__device__ __forceinline__ float rowsum16(float v) {
    #pragma unroll
    for (int o = 8; o > 0; o >>= 1)
        v += __shfl_xor_sync(0xffffffffu, v, o);
    return v;
}

__global__ __launch_bounds__(NTHREADS, 1)
void sdpa_kernel(const float* __restrict__ Q, const float* __restrict__ K,
                 const float* __restrict__ V, const unsigned* __restrict__ Mask,
                 float* __restrict__ O)
{
    extern __shared__ float sm[];
    float* Qs = sm;                    // DIM*RS
    float* Ks = Qs + DIM * RS;         // DIM*RS
    float* Vs = Ks + DIM * RS;         // BK*DIM
    float* Ps = Vs + BK * DIM;         // BQ*65
    float* Ms = Ps + BQ * 65;          // BK

    const int b    = blockIdx.y;
    const int qb   = gridDim.x - 1 - blockIdx.x;   // longest CTAs scheduled first
    const int tid  = threadIdx.x;
    const int warp = tid >> 5;
    const int lane = tid & 31;
    const int tx   = tid & 15;   // column group
    const int ty   = tid >> 4;   // row group

    const float* Qg = Q + ((size_t)b * SEQ + (size_t)qb * BQ) * DIM;
    const float* Kg = K + (size_t)b * SEQ * DIM;
    const float* Vg = V + (size_t)b * SEQ * DIM;
    const unsigned* Mg = Mask + (size_t)b * SEQ;

    const int q8 = lane >> 2;    // 0..7 : row within warp's 8-row group
    const int dg = lane & 3;     // 0..3 : float4 slot within 16-float d-chunk

    // ---- load Q block transposed: Qs[d][q] ----
    {
        const int row = warp * 8 + q8;               // warp owns 8 rows
        #pragma unroll
        for (int it = 0; it < 16; it++) {            // 16 d-chunks of 16 floats
            int d0 = it * 16 + dg * 4;
            float4 v = *(const float4*)(Qg + row * DIM + d0);
            Qs[(d0 + 0) * RS + row] = v.x;
            Qs[(d0 + 1) * RS + row] = v.y;
            Qs[(d0 + 2) * RS + row] = v.z;
            Qs[(d0 + 3) * RS + row] = v.w;
        }
    }

    float acc[4][16];
    #pragma unroll
    for (int i = 0; i < 4; i++)
        #pragma unroll
        for (int u = 0; u < 16; u++) acc[i][u] = 0.f;
    float mrow[4], lrow[4];
    #pragma unroll
    for (int i = 0; i < 4; i++) { mrow[i] = -1e30f; lrow[i] = 0.f; }

    const int qg0 = qb * BQ + 4 * ty;

    for (int kb = 0; kb <= qb; kb++) {
        __syncthreads();   // prev PV done reading Vs/Ps before overwrite

        // ---- load K block transposed: Ks[d][k] ----
        {
            const float* Kb = Kg + (size_t)kb * BK * DIM;
            const int row = warp * 8 + q8;
            #pragma unroll
            for (int it = 0; it < 16; it++) {
                int d0 = it * 16 + dg * 4;
                float4 v = *(const float4*)(Kb + row * DIM + d0);
                Ks[(d0 + 0) * RS + row] = v.x;
                Ks[(d0 + 1) * RS + row] = v.y;
                Ks[(d0 + 2) * RS + row] = v.z;
                Ks[(d0 + 3) * RS + row] = v.w;
            }
        }
        // ---- load V block natural: Vs[k][d] ----
        {
            const float* Vb = Vg + (size_t)kb * BK * DIM;
            #pragma unroll
            for (int it = 0; it < 16; it++) {
                int f = tid + NTHREADS * it;          // float4 index
                int row = f >> 6;
                int c4  = (f & 63) * 4;
                *(float4*)(Vs + row * DIM + c4) = *(const float4*)(Vb + row * DIM + c4);
            }
        }
        // ---- padding mask (robust to int32 {0,1} or f32 {0.0,1.0}) ----
        if (tid < BK) Ms[tid] = (Mg[kb * BK + tid] != 0u) ? 1.f : 0.f;

        __syncthreads();

        // ---- S = Q K^T / 16 : per-thread 4x4 tile ----
        float s[4][4];
        #pragma unroll
        for (int i = 0; i < 4; i++)
            #pragma unroll
            for (int j = 0; j < 4; j++) s[i][j] = 0.f;

        {
            const float* ap = Qs + 4 * ty;
            const float* bp = Ks + tx;
            #pragma unroll 8
            for (int kd = 0; kd < DIM; kd++) {
                float a0 = ap[kd * RS + 0];
                float a1 = ap[kd * RS + 1];
                float a2 = ap[kd * RS + 2];
                float a3 = ap[kd * RS + 3];
                float b0 = bp[kd * RS + 0];
                float b1 = bp[kd * RS + 16];
                float b2 = bp[kd * RS + 32];
                float b3 = bp[kd * RS + 48];
                s[0][0] += a0 * b0; s[0][1] += a0 * b1; s[0][2] += a0 * b2; s[0][3] += a0 * b3;
                s[1][0] += a1 * b0; s[1][1] += a1 * b1; s[1][2] += a1 * b2; s[1][3] += a1 * b3;
                s[2][0] += a2 * b0; s[2][1] += a2 * b1; s[2][2] += a2 * b2; s[2][3] += a2 * b3;
                s[3][0] += a3 * b0; s[3][1] += a3 * b1; s[3][2] += a3 * b2; s[3][3] += a3 * b3;
            }
        }

        const bool fullblk = (kb < qb);   // strictly-below-diagonal: causal always true
        float mv[4];
        #pragma unroll
        for (int j = 0; j < 4; j++) mv[j] = Ms[tx + 16 * j];

        #pragma unroll
        for (int i = 0; i < 4; i++) {
            const int qg = qg0 + i;
            // mask into sentinel
            #pragma unroll
            for (int j = 0; j < 4; j++) {
                int kg = kb * BK + tx + 16 * j;
                bool valid = (mv[j] != 0.f) && (fullblk || kg <= qg);
                float sv = s[i][j] * 0.0625f;   // 1/sqrt(256)
                s[i][j] = valid ? sv : -1e30f;
            }
            float mx = fmaxf(fmaxf(s[i][0], s[i][1]), fmaxf(s[i][2], s[i][3]));
            mx = rowmax16(mx);
            float mnew = fmaxf(mrow[i], mx);
            float corr = __expf(mrow[i] - mnew);  // -1e30 - -1e30 = 0 -> 1 (l=0, harmless)
            float rs = 0.f;
            #pragma unroll
            for (int j = 0; j < 4; j++) {
                float p = (s[i][j] > -1e29f) ? __expf(s[i][j] - mnew) : 0.f;
                rs += p;
                Ps[(4 * ty + i) * 65 + tx + 16 * j] = p;
            }
            rs = rowsum16(rs);
            lrow[i] = lrow[i] * corr + rs;
            mrow[i] = mnew;
            #pragma unroll
            for (int u = 0; u < 16; u++) acc[i][u] *= corr;
        }

        __syncthreads();   // Ps visible to all tx of each row group

        // ---- acc += P V ----
        {
            const float* pp = Ps + 4 * ty * 65;
            const float* vp = Vs + tx;
            #pragma unroll 2
            for (int kk = 0; kk < BK; kk++) {
                float p0 = pp[0 * 65 + kk];
                float p1 = pp[1 * 65 + kk];
                float p2 = pp[2 * 65 + kk];
                float p3 = pp[3 * 65 + kk];
                #pragma unroll
                for (int u = 0; u < 16; u++) {
                    float vv = vp[kk * DIM + 16 * u];
                    acc[0][u] += p0 * vv;
                    acc[1][u] += p1 * vv;
                    acc[2][u] += p2 * vv;
                    acc[3][u] += p3 * vv;
                }
            }
        }
    }

    // ---- epilogue: out = acc / (l + eps) ----
    #pragma unroll
    for (int i = 0; i < 4; i++) {
        float inv = 1.0f / (lrow[i] + 1e-7f);
        float* op = O + ((size_t)b * SEQ + (size_t)(qg0 + i)) * DIM + tx;
        #pragma unroll
        for (int u = 0; u < 16; u++)
            op[16 * u] = acc[i][u] * inv;
    }
}

extern "C" void kernel_launch(void* const* d_in, const int* in_sizes, int n_in,
                              void* d_out, int out_size)
{
    const float*    Q  = (const float*)d_in[0];
    const float*    K  = (const float*)d_in[1];
    const float*    V  = (const float*)d_in[2];
    const unsigned* Mk = (const unsigned*)d_in[3];
    float* O = (float*)d_out;

    size_t smem = SMEM_FLOATS * sizeof(float);   // 217,600 B
    cudaFuncSetAttribute(sdpa_kernel, cudaFuncAttributeMaxDynamicSharedMemorySize, (int)smem);

    dim3 grid(SEQ / BQ, NBAT);
    sdpa_kernel<<<grid, NTHREADS, smem>>>(Q, K, V, Mk, O);
}